// round 9
// baseline (speedup 1.0000x reference)
#include <cuda_runtime.h>
#include <cuda_bf16.h>
#include <cuda_fp8.h>
#include <stdint.h>
#include <stddef.h>
#include <math.h>

#define BATCH 8
#define NN 2048
#define DD 768
#define NTILE 16
#define NPAIRS (NTILE * (NTILE + 1) / 2)   // 136 upper-triangle tiles

// ---------------- device scratch (allocation-free rule) ----------------
__device__ __nv_bfloat16 g_midn[(size_t)BATCH * NN * DD];   // normalized mid (bf16)
__device__ unsigned char g_ftp8[(size_t)BATCH * DD * NN];   // final^T (e4m3), [d][n]
__device__ unsigned char g_expb[(size_t)BATCH * NN * NN];   // e4m3 exp(sim)
__device__ unsigned      g_confbits[BATCH * NN];            // ordered-uint row max
__device__ float         g_conf[BATCH * NN];                // row max (confidence)
__device__ float         g_rinv[BATCH * NN];                // 1 / row sum of exp

__device__ __forceinline__ uint32_t s2u(const void* p) {
    return (uint32_t)__cvta_generic_to_shared(p);
}
__device__ __forceinline__ void cpa16(void* dst, const void* src) {
    asm volatile("cp.async.cg.shared.global [%0], [%1], 16;"
                 :: "r"(s2u(dst)), "l"(src));
}
#define CP_COMMIT() asm volatile("cp.async.commit_group;")
#define CP_WAIT(n)  asm volatile("cp.async.wait_group %0;" :: "n"(n))

// monotonic float<->uint for atomicMax
__device__ __forceinline__ unsigned fenc(float x) {
    unsigned b = __float_as_uint(x);
    return (b & 0x80000000u) ? ~b : (b | 0x80000000u);
}
__device__ __forceinline__ float fdec(unsigned e) {
    unsigned b = (e & 0x80000000u) ? (e ^ 0x80000000u) : ~e;
    return __uint_as_float(b);
}
__device__ __forceinline__ uint32_t pk2f8(float a, float b2) {
    return (uint32_t)__nv_cvt_float2_to_fp8x2(make_float2(a, b2),
                                              __NV_SATFINITE, __NV_E4M3);
}
__device__ __forceinline__ uint32_t pk4f8(float a, float b2, float c, float d) {
    return pk2f8(a, b2) | (pk2f8(c, d) << 16);
}
__device__ __forceinline__ float2 up2f8(uint16_t x) {
    __half2_raw hr = __nv_cvt_fp8x2_to_halfraw2((__nv_fp8x2_storage_t)x, __NV_E4M3);
    return __half22float2(*(__half2*)&hr);
}

// ---------------------------------------------------------------------------
// Kernel 1: L2-normalize mid along D -> bf16; reset g_confbits.
// ---------------------------------------------------------------------------
__global__ void norm_kernel(const float* __restrict__ mid) {
    const int row = blockIdx.x;
    if (threadIdx.x == 0) g_confbits[row] = fenc(-INFINITY);
    const float* x = mid + (size_t)row * DD;
    __nv_bfloat16* y = g_midn + (size_t)row * DD;

    float s = 0.f;
    for (int i = threadIdx.x; i < DD; i += blockDim.x) {
        float v = x[i];
        s += v * v;
    }
    __shared__ float sh[32];
    #pragma unroll
    for (int o = 16; o > 0; o >>= 1) s += __shfl_xor_sync(0xffffffffu, s, o);
    const int w = threadIdx.x >> 5, l = threadIdx.x & 31;
    if (l == 0) sh[w] = s;
    __syncthreads();
    if (w == 0) {
        float v = (threadIdx.x < (blockDim.x >> 5)) ? sh[threadIdx.x] : 0.f;
        #pragma unroll
        for (int o = 16; o > 0; o >>= 1) v += __shfl_xor_sync(0xffffffffu, v, o);
        if (threadIdx.x == 0) sh[0] = v;
    }
    __syncthreads();
    const float inv = 1.0f / fmaxf(sqrtf(sh[0]), 1e-12f);
    for (int i = threadIdx.x; i < DD; i += blockDim.x)
        y[i] = __float2bfloat16(x[i] * inv);
}

// ---------------------------------------------------------------------------
// Kernel 1b: transpose final fp32 [n][d] -> e4m3 [d][n].
// ---------------------------------------------------------------------------
__global__ void transpose_fp8(const float* __restrict__ fin) {
    __shared__ float t[32][33];
    const int b = blockIdx.z;
    const int d0 = blockIdx.x * 32, n0 = blockIdx.y * 32;
    const float* F = fin + (size_t)b * NN * DD;
    unsigned char* T = g_ftp8 + (size_t)b * DD * NN;
    const int x = threadIdx.x, y = threadIdx.y;
    #pragma unroll
    for (int i = 0; i < 4; i++)
        t[y + 8 * i][x] = F[(size_t)(n0 + y + 8 * i) * DD + d0 + x];
    __syncthreads();
    uint32_t word = pk4f8(t[y * 4 + 0][x], t[y * 4 + 1][x],
                          t[y * 4 + 2][x], t[y * 4 + 3][x]);
    *(uint32_t*)(T + (size_t)(d0 + x) * NN + n0 + y * 4) = word;
}

// ---------------------------------------------------------------------------
// Kernel 2: sim GEMM (upper-triangle tiles, bf16 HMMA, k-chunk = 64 halves)
// -> exp(sim) e4m3 + row-max atomics. SMEM-staged symmetric epilogue.
// ---------------------------------------------------------------------------
#define KT_SIM (DD / 64)                   // 12 iterations
#define STG    8192                        // halves per stage tile (128x64)
#define SIM_SMEM (128 * 129 * 4)           // 66048 B (>= 4*STG*2 = 65536)

__global__ __launch_bounds__(256) void sim_mma() {
    extern __shared__ char dsm[];
    __nv_bfloat16* As = (__nv_bfloat16*)dsm;          // [2][STG]
    __nv_bfloat16* Bs = As + 2 * STG;                 // [2][STG]
    float* T = (float*)dsm;                           // [128][129], reused

    int t = blockIdx.x, bi = 0, rem = NTILE;
    while (t >= rem) { t -= rem; rem--; bi++; }
    const int bj = bi + t;
    const int b = blockIdx.z;
    const int row0 = bi << 7, col0 = bj << 7;
    const bool diag = (bi == bj);
    const __nv_bfloat16* Ab = g_midn + (size_t)b * NN * DD;

    const int tid = threadIdx.x, lane = tid & 31, wid = tid >> 5;
    const int wm = (wid >> 1) << 5;
    const int wn = (wid & 1) << 6;

    float acc[2][8][4];
    #pragma unroll
    for (int i = 0; i < 2; i++)
        #pragma unroll
        for (int j = 0; j < 8; j++)
            #pragma unroll
            for (int k = 0; k < 4; k++) acc[i][j][k] = 0.f;

    // loader: 1024 16B-chunks per tile, 4 per thread
    int lrow[4], lgo[4], lso[4];
    #pragma unroll
    for (int q = 0; q < 4; q++) {
        int chunk = tid + 256 * q;
        int r = chunk & 127, c = chunk >> 7;           // c in 0..7
        lrow[q] = r;
        lgo[q] = c * 8;                                 // gmem offset (halves)
        lso[q] = (r << 6) | ((c ^ (r & 7)) << 3);       // smem offset (halves)
    }

    #define SIM_LOAD(kt, p)                                                     \
        do {                                                                    \
            _Pragma("unroll")                                                   \
            for (int q = 0; q < 4; q++) {                                       \
                cpa16(&As[(p) * STG + lso[q]],                                  \
                      Ab + (size_t)(row0 + lrow[q]) * DD + (kt) + lgo[q]);      \
                cpa16(&Bs[(p) * STG + lso[q]],                                  \
                      Ab + (size_t)(col0 + lrow[q]) * DD + (kt) + lgo[q]);      \
            }                                                                   \
        } while (0)

    SIM_LOAD(0, 0);
    CP_COMMIT();

    for (int kti = 0; kti < KT_SIM; kti++) {
        const int p = kti & 1;
        if (kti + 1 < KT_SIM) {
            SIM_LOAD((kti + 1) * 64, p ^ 1);
            CP_COMMIT();
            CP_WAIT(1);
        } else {
            CP_WAIT(0);
        }
        __syncthreads();

        #pragma unroll
        for (int ks = 0; ks < 4; ks++) {
            uint32_t af[2][4];
            #pragma unroll
            for (int i = 0; i < 2; i++) {
                int row = wm + i * 16 + (lane & 15);
                int kc  = ks * 2 + (lane >> 4);                  // chunk idx 0..7
                uint32_t ad = s2u(&As[p * STG +
                    ((row << 6) | ((kc ^ (row & 7)) << 3))]);
                asm volatile("ldmatrix.sync.aligned.m8n8.x4.shared.b16 {%0,%1,%2,%3}, [%4];"
                    : "=r"(af[i][0]), "=r"(af[i][1]), "=r"(af[i][2]), "=r"(af[i][3])
                    : "r"(ad));
            }
            uint32_t bf[8][2];
            #pragma unroll
            for (int j2 = 0; j2 < 4; j2++) {
                int row = wn + j2 * 16 + (lane & 7) + (((lane >> 4) & 1) << 3);
                int kc  = ks * 2 + ((lane >> 3) & 1);
                uint32_t bd = s2u(&Bs[p * STG +
                    ((row << 6) | ((kc ^ (row & 7)) << 3))]);
                asm volatile("ldmatrix.sync.aligned.m8n8.x4.shared.b16 {%0,%1,%2,%3}, [%4];"
                    : "=r"(bf[j2 * 2][0]), "=r"(bf[j2 * 2][1]),
                      "=r"(bf[j2 * 2 + 1][0]), "=r"(bf[j2 * 2 + 1][1])
                    : "r"(bd));
            }
            #pragma unroll
            for (int i = 0; i < 2; i++)
                #pragma unroll
                for (int j = 0; j < 8; j++)
                    asm volatile(
                        "mma.sync.aligned.m16n8k16.row.col.f32.bf16.bf16.f32 "
                        "{%0,%1,%2,%3}, {%4,%5,%6,%7}, {%8,%9}, {%0,%1,%2,%3};"
                        : "+f"(acc[i][j][0]), "+f"(acc[i][j][1]),
                          "+f"(acc[i][j][2]), "+f"(acc[i][j][3])
                        : "r"(af[i][0]), "r"(af[i][1]), "r"(af[i][2]), "r"(af[i][3]),
                          "r"(bf[j][0]), "r"(bf[j][1]));
        }
        __syncthreads();
    }

    // ---- stage fp32 tile (diag zeroed) in SMEM ----
    const int gr = lane >> 2, gc = (lane & 3) << 1;
    #pragma unroll
    for (int i = 0; i < 2; i++) {
        const int rl = wm + i * 16 + gr;
        #pragma unroll
        for (int j = 0; j < 8; j++) {
            const int cl = wn + j * 8 + gc;
            const int gofs = (row0 + rl) - (col0 + cl);
            T[rl * 129 + cl]           = (gofs == 0)  ? 0.f : acc[i][j][0];
            T[rl * 129 + cl + 1]       = (gofs == 1)  ? 0.f : acc[i][j][1];
            T[(rl + 8) * 129 + cl]     = (gofs == -8) ? 0.f : acc[i][j][2];
            T[(rl + 8) * 129 + cl + 1] = (gofs == -7) ? 0.f : acc[i][j][3];
        }
    }
    __syncthreads();

    // ---- row pass: write exp(tile) as e4m3 + row-max atomics ----
    {
        const int rr = tid >> 1, cs = (tid & 1) << 6;
        float mx = -INFINITY;
        uint32_t* dst = (uint32_t*)(g_expb + (size_t)b * NN * NN
                                    + (size_t)(row0 + rr) * NN + col0 + cs);
        #pragma unroll
        for (int c = 0; c < 64; c += 4) {
            float v0 = T[rr * 129 + cs + c + 0];
            float v1 = T[rr * 129 + cs + c + 1];
            float v2 = T[rr * 129 + cs + c + 2];
            float v3 = T[rr * 129 + cs + c + 3];
            mx = fmaxf(mx, fmaxf(fmaxf(v0, v1), fmaxf(v2, v3)));
            dst[c >> 2] = pk4f8(__expf(v0), __expf(v1), __expf(v2), __expf(v3));
        }
        atomicMax(&g_confbits[b * NN + row0 + rr], fenc(mx));
    }

    // ---- col pass (mirror) for off-diagonal tiles ----
    if (!diag) {
        const int cc = tid >> 1, rs = (tid & 1) << 6;
        float mx = -INFINITY;
        uint32_t* dst = (uint32_t*)(g_expb + (size_t)b * NN * NN
                                    + (size_t)(col0 + cc) * NN + row0 + rs);
        #pragma unroll
        for (int r = 0; r < 64; r += 4) {
            float v0 = T[(rs + r + 0) * 129 + cc];
            float v1 = T[(rs + r + 1) * 129 + cc];
            float v2 = T[(rs + r + 2) * 129 + cc];
            float v3 = T[(rs + r + 3) * 129 + cc];
            mx = fmaxf(mx, fmaxf(fmaxf(v0, v1), fmaxf(v2, v3)));
            dst[r >> 2] = pk4f8(__expf(v0), __expf(v1), __expf(v2), __expf(v3));
        }
        atomicMax(&g_confbits[b * NN + col0 + cc], fenc(mx));
    }
}

// ---------------------------------------------------------------------------
// Kernel 3: row sums of e4m3 exp -> rinv; conf from confbits.
// ---------------------------------------------------------------------------
__global__ void rowsum_kernel() {
    const int row = blockIdx.x;
    const uint4* p = (const uint4*)(g_expb + (size_t)row * NN) + threadIdx.x;
    uint4 v = p[0];
    float s = 0.f;
    const uint32_t w4[4] = {v.x, v.y, v.z, v.w};
    #pragma unroll
    for (int h = 0; h < 4; h++) {
        float2 a = up2f8((uint16_t)(w4[h] & 0xFFFF));
        float2 b2 = up2f8((uint16_t)(w4[h] >> 16));
        s += (a.x + a.y) + (b2.x + b2.y);
    }
    __shared__ float sh[4];
    #pragma unroll
    for (int o = 16; o > 0; o >>= 1) s += __shfl_xor_sync(0xffffffffu, s, o);
    const int w = threadIdx.x >> 5, l = threadIdx.x & 31;
    if (l == 0) sh[w] = s;
    __syncthreads();
    if (threadIdx.x == 0) {
        float v2 = sh[0] + sh[1] + sh[2] + sh[3];
        g_conf[row] = fdec(g_confbits[row]);
        g_rinv[row] = 1.0f / v2;
    }
}

// ---------------------------------------------------------------------------
// Kernel 4: refined = (E @ F) * rinv ; out = cw*refined + (1-cw)*final.
// fp8 e4m3 QMMA m16n8k32, k-chunk = 128 bytes (16 iterations).
// ---------------------------------------------------------------------------
#define KT_OUT (NN / 128)                  // 16 iterations
#define STG8   16384                       // bytes per stage tile (128x128)
#define OUT_SMEM (4 * STG8)                // 65536

__global__ __launch_bounds__(256) void out_mma(const float* __restrict__ fin,
                                               float* __restrict__ out) {
    extern __shared__ char dsm[];
    unsigned char* Es = (unsigned char*)dsm;          // [2][STG8]
    unsigned char* Fs = Es + 2 * STG8;                // [2][STG8]
    const int b = blockIdx.z;
    const int row0 = blockIdx.y << 7;   // n rows
    const int col0 = blockIdx.x << 7;   // d cols
    const unsigned char* Eb = g_expb + (size_t)b * NN * NN;
    const unsigned char* Tb = g_ftp8 + (size_t)b * DD * NN;

    const int tid = threadIdx.x, lane = tid & 31, wid = tid >> 5;
    const int wm = (wid >> 1) << 5;
    const int wn = (wid & 1) << 6;

    float acc[2][8][4];
    #pragma unroll
    for (int i = 0; i < 2; i++)
        #pragma unroll
        for (int j = 0; j < 8; j++)
            #pragma unroll
            for (int k = 0; k < 4; k++) acc[i][j][k] = 0.f;

    int lrow[4], lgo[4], lso[4];
    #pragma unroll
    for (int q = 0; q < 4; q++) {
        int chunk = tid + 256 * q;
        int r = chunk & 127, c = chunk >> 7;           // c in 0..7
        lrow[q] = r;
        lgo[q] = c * 16;                                // gmem offset (bytes)
        lso[q] = (r << 7) | ((c ^ (r & 7)) << 4);       // smem offset (bytes)
    }

    #define OUT_LOAD(kt, p)                                                     \
        do {                                                                    \
            _Pragma("unroll")                                                   \
            for (int q = 0; q < 4; q++) {                                       \
                cpa16(&Es[(p) * STG8 + lso[q]],                                 \
                      Eb + (size_t)(row0 + lrow[q]) * NN + (kt) + lgo[q]);      \
                cpa16(&Fs[(p) * STG8 + lso[q]],                                 \
                      Tb + (size_t)(col0 + lrow[q]) * NN + (kt) + lgo[q]);      \
            }                                                                   \
        } while (0)

    OUT_LOAD(0, 0);
    CP_COMMIT();

    for (int kti = 0; kti < KT_OUT; kti++) {
        const int p = kti & 1;
        if (kti + 1 < KT_OUT) {
            OUT_LOAD((kti + 1) * 128, p ^ 1);
            CP_COMMIT();
            CP_WAIT(1);
        } else {
            CP_WAIT(0);
        }
        __syncthreads();

        #pragma unroll
        for (int ks = 0; ks < 4; ks++) {
            uint32_t af[2][4];
            #pragma unroll
            for (int i = 0; i < 2; i++) {
                int row = wm + i * 16 + (lane & 15);
                int c16 = ks * 2 + (lane >> 4);
                uint32_t ad = s2u(&Es[p * STG8 +
                    ((row << 7) | ((c16 ^ (row & 7)) << 4))]);
                asm volatile("ldmatrix.sync.aligned.m8n8.x4.shared.b16 {%0,%1,%2,%3}, [%4];"
                    : "=r"(af[i][0]), "=r"(af[i][1]), "=r"(af[i][2]), "=r"(af[i][3])
                    : "r"(ad));
            }
            uint32_t bf[8][2];
            #pragma unroll
            for (int j2 = 0; j2 < 4; j2++) {
                int row = wn + j2 * 16 + (lane & 7) + (((lane >> 4) & 1) << 3);
                int c16 = ks * 2 + ((lane >> 3) & 1);
                uint32_t bd = s2u(&Fs[p * STG8 +
                    ((row << 7) | ((c16 ^ (row & 7)) << 4))]);
                asm volatile("ldmatrix.sync.aligned.m8n8.x4.shared.b16 {%0,%1,%2,%3}, [%4];"
                    : "=r"(bf[j2 * 2][0]), "=r"(bf[j2 * 2][1]),
                      "=r"(bf[j2 * 2 + 1][0]), "=r"(bf[j2 * 2 + 1][1])
                    : "r"(bd));
            }
            #pragma unroll
            for (int i = 0; i < 2; i++)
                #pragma unroll
                for (int j = 0; j < 8; j++)
                    asm volatile(
                        "mma.sync.aligned.m16n8k32.row.col.f32.e4m3.e4m3.f32 "
                        "{%0,%1,%2,%3}, {%4,%5,%6,%7}, {%8,%9}, {%0,%1,%2,%3};"
                        : "+f"(acc[i][j][0]), "+f"(acc[i][j][1]),
                          "+f"(acc[i][j][2]), "+f"(acc[i][j][3])
                        : "r"(af[i][0]), "r"(af[i][1]), "r"(af[i][2]), "r"(af[i][3]),
                          "r"(bf[j][0]), "r"(bf[j][1]));
        }
        __syncthreads();
    }

    const float* F32 = fin + (size_t)b * NN * DD;
    float* O = out + (size_t)b * NN * DD;
    const int gr = lane >> 2, gc = (lane & 3) << 1;
    #pragma unroll
    for (int i = 0; i < 2; i++) {
        #pragma unroll
        for (int half = 0; half < 2; half++) {
            int r = row0 + wm + i * 16 + gr + half * 8;
            const float cw  = g_conf[b * NN + r];
            const float inv = g_rinv[b * NN + r];
            #pragma unroll
            for (int j = 0; j < 8; j++) {
                int c = col0 + wn + j * 8 + gc;
                float2 f = *(const float2*)(F32 + (size_t)r * DD + c);
                float2 o;
                o.x = cw * (acc[i][j][half * 2 + 0] * inv) + (1.0f - cw) * f.x;
                o.y = cw * (acc[i][j][half * 2 + 1] * inv) + (1.0f - cw) * f.y;
                *(float2*)(O + (size_t)r * DD + c) = o;
            }
        }
    }
}

// ---------------------------------------------------------------------------
extern "C" void kernel_launch(void* const* d_in, const int* in_sizes, int n_in,
                              void* d_out, int out_size) {
    const float* final_f = (const float*)d_in[0];
    const float* mid_f   = (const float*)d_in[1];
    float* out = (float*)d_out;

    static int configured = 0;
    if (!configured) {
        cudaFuncSetAttribute(sim_mma, cudaFuncAttributeMaxDynamicSharedMemorySize,
                             SIM_SMEM);
        cudaFuncSetAttribute(out_mma, cudaFuncAttributeMaxDynamicSharedMemorySize,
                             OUT_SMEM);
        configured = 1;
    }

    norm_kernel<<<BATCH * NN, 256>>>(mid_f);
    transpose_fp8<<<dim3(DD / 32, NN / 32, BATCH), dim3(32, 8)>>>(final_f);

    sim_mma<<<dim3(NPAIRS, 1, BATCH), 256, SIM_SMEM>>>();

    rowsum_kernel<<<BATCH * NN, 128>>>();

    out_mma<<<dim3(DD / 128, NN / 128, BATCH), 256, OUT_SMEM>>>(final_f, out);
}

// round 10
// speedup vs baseline: 1.1525x; 1.1525x over previous
#include <cuda_runtime.h>
#include <cuda_bf16.h>
#include <cuda_fp8.h>
#include <stdint.h>
#include <stddef.h>
#include <math.h>

#define BATCH 8
#define NN 2048
#define DD 768
#define NTILE 16
#define NPAIRS (NTILE * (NTILE + 1) / 2)   // 136 upper-triangle tiles

// ---------------- device scratch (allocation-free rule) ----------------
__device__ __nv_bfloat16 g_midn[(size_t)BATCH * NN * DD];   // normalized mid (bf16)
__device__ unsigned char g_ftp8[(size_t)BATCH * DD * NN];   // final^T (e4m3), [d][n]
__device__ unsigned char g_expb[(size_t)BATCH * NN * NN];   // e4m3 exp(sim)
__device__ unsigned      g_confbits[BATCH * NN];            // ordered-uint row max
__device__ float         g_conf[BATCH * NN];                // row max (confidence)
__device__ float         g_rinv[BATCH * NN];                // 1 / row sum of exp

__device__ __forceinline__ uint32_t s2u(const void* p) {
    return (uint32_t)__cvta_generic_to_shared(p);
}
__device__ __forceinline__ void cpa16(void* dst, const void* src) {
    asm volatile("cp.async.cg.shared.global [%0], [%1], 16;"
                 :: "r"(s2u(dst)), "l"(src));
}
#define CP_COMMIT() asm volatile("cp.async.commit_group;")
#define CP_WAIT(n)  asm volatile("cp.async.wait_group %0;" :: "n"(n))

// monotonic float<->uint for atomicMax
__device__ __forceinline__ unsigned fenc(float x) {
    unsigned b = __float_as_uint(x);
    return (b & 0x80000000u) ? ~b : (b | 0x80000000u);
}
__device__ __forceinline__ float fdec(unsigned e) {
    unsigned b = (e & 0x80000000u) ? (e ^ 0x80000000u) : ~e;
    return __uint_as_float(b);
}
__device__ __forceinline__ uint32_t pk2f8(float a, float b2) {
    return (uint32_t)__nv_cvt_float2_to_fp8x2(make_float2(a, b2),
                                              __NV_SATFINITE, __NV_E4M3);
}
__device__ __forceinline__ uint32_t pk4f8(float a, float b2, float c, float d) {
    return pk2f8(a, b2) | (pk2f8(c, d) << 16);
}
__device__ __forceinline__ float2 up2f8(uint16_t x) {
    __half2_raw hr = __nv_cvt_fp8x2_to_halfraw2((__nv_fp8x2_storage_t)x, __NV_E4M3);
    return __half22float2(*(__half2*)&hr);
}

// swizzled index (halves) for bf16 tiles with 32-half (64B) rows
__device__ __forceinline__ int swA(int row, int kh) {
    return (row << 5) | ((((kh >> 3) ^ ((row >> 1) & 3)) << 3));
}
// swizzled byte offset for fp8 tiles: 128 rows x 64 bytes, 16B chunks
__device__ __forceinline__ int off8(int r, int c16) {
    return (r << 6) | ((((c16) ^ ((r >> 1) & 3)) & 3) << 4);
}

// ---------------------------------------------------------------------------
// Kernel 1: L2-normalize mid along D -> bf16; reset g_confbits.
// ---------------------------------------------------------------------------
__global__ void norm_kernel(const float* __restrict__ mid) {
    const int row = blockIdx.x;
    if (threadIdx.x == 0) g_confbits[row] = fenc(-INFINITY);
    const float* x = mid + (size_t)row * DD;
    __nv_bfloat16* y = g_midn + (size_t)row * DD;

    float s = 0.f;
    for (int i = threadIdx.x; i < DD; i += blockDim.x) {
        float v = x[i];
        s += v * v;
    }
    __shared__ float sh[32];
    #pragma unroll
    for (int o = 16; o > 0; o >>= 1) s += __shfl_xor_sync(0xffffffffu, s, o);
    const int w = threadIdx.x >> 5, l = threadIdx.x & 31;
    if (l == 0) sh[w] = s;
    __syncthreads();
    if (w == 0) {
        float v = (threadIdx.x < (blockDim.x >> 5)) ? sh[threadIdx.x] : 0.f;
        #pragma unroll
        for (int o = 16; o > 0; o >>= 1) v += __shfl_xor_sync(0xffffffffu, v, o);
        if (threadIdx.x == 0) sh[0] = v;
    }
    __syncthreads();
    const float inv = 1.0f / fmaxf(sqrtf(sh[0]), 1e-12f);
    for (int i = threadIdx.x; i < DD; i += blockDim.x)
        y[i] = __float2bfloat16(x[i] * inv);
}

// ---------------------------------------------------------------------------
// Kernel 1b: transpose final fp32 [n][d] -> e4m3 [d][n].
// ---------------------------------------------------------------------------
__global__ void transpose_fp8(const float* __restrict__ fin) {
    __shared__ float t[32][33];
    const int b = blockIdx.z;
    const int d0 = blockIdx.x * 32, n0 = blockIdx.y * 32;
    const float* F = fin + (size_t)b * NN * DD;
    unsigned char* T = g_ftp8 + (size_t)b * DD * NN;
    const int x = threadIdx.x, y = threadIdx.y;
    #pragma unroll
    for (int i = 0; i < 4; i++)
        t[y + 8 * i][x] = F[(size_t)(n0 + y + 8 * i) * DD + d0 + x];
    __syncthreads();
    uint32_t word = pk4f8(t[y * 4 + 0][x], t[y * 4 + 1][x],
                          t[y * 4 + 2][x], t[y * 4 + 3][x]);
    *(uint32_t*)(T + (size_t)(d0 + x) * NN + n0 + y * 4) = word;
}

// ---------------------------------------------------------------------------
// Kernel 2: sim GEMM (upper-triangle tiles, bf16 HMMA, k-chunk = 32 halves,
// 3-stage cp.async pipeline, 1 sync/iter) -> exp(sim) e4m3 + row-max atomics.
// ---------------------------------------------------------------------------
#define KT_SIM (DD / 32)                   // 24 iterations
#define STG    4096                        // halves per stage tile (128x32)
#define SIM_SMEM (128 * 129 * 4)           // 66048 B (>= 3 stages * 16KB = 49152)

__global__ __launch_bounds__(256) void sim_mma() {
    extern __shared__ char dsm[];
    __nv_bfloat16* As = (__nv_bfloat16*)dsm;          // [3][STG]
    __nv_bfloat16* Bs = As + 3 * STG;                 // [3][STG]
    float* T = (float*)dsm;                           // [128][129], reused

    int t = blockIdx.x, bi = 0, rem = NTILE;
    while (t >= rem) { t -= rem; rem--; bi++; }
    const int bj = bi + t;
    const int b = blockIdx.z;
    const int row0 = bi << 7, col0 = bj << 7;
    const bool diag = (bi == bj);
    const __nv_bfloat16* Ab = g_midn + (size_t)b * NN * DD;

    const int tid = threadIdx.x, lane = tid & 31, wid = tid >> 5;
    const int wm = (wid >> 1) << 5;
    const int wn = (wid & 1) << 6;

    float acc[2][8][4];
    #pragma unroll
    for (int i = 0; i < 2; i++)
        #pragma unroll
        for (int j = 0; j < 8; j++)
            #pragma unroll
            for (int k = 0; k < 4; k++) acc[i][j][k] = 0.f;

    const int r0q = tid & 127,          c0q = (tid >> 7) << 3;
    const int r1q = (tid + 256) & 127,  c1q = ((tid + 256) >> 7) << 3;

    #define SIM_LOAD(kt, p)                                                           \
        do {                                                                          \
            cpa16(&As[(p) * STG + swA(r0q, c0q)], Ab + (size_t)(row0 + r0q) * DD + (kt) + c0q); \
            cpa16(&As[(p) * STG + swA(r1q, c1q)], Ab + (size_t)(row0 + r1q) * DD + (kt) + c1q); \
            cpa16(&Bs[(p) * STG + swA(r0q, c0q)], Ab + (size_t)(col0 + r0q) * DD + (kt) + c0q); \
            cpa16(&Bs[(p) * STG + swA(r1q, c1q)], Ab + (size_t)(col0 + r1q) * DD + (kt) + c1q); \
        } while (0)

    SIM_LOAD(0, 0);
    CP_COMMIT();
    SIM_LOAD(32, 1);
    CP_COMMIT();

    int p = 0, pw = 2;                                  // compute stage, write stage
    for (int kti = 0; kti < KT_SIM; kti++) {
        CP_WAIT(1);
        __syncthreads();
        if (kti + 2 < KT_SIM) SIM_LOAD((kti + 2) * 32, pw);
        CP_COMMIT();

        #pragma unroll
        for (int ks = 0; ks < 2; ks++) {
            uint32_t af[2][4];
            #pragma unroll
            for (int i = 0; i < 2; i++) {
                int row = wm + i * 16 + (lane & 15);
                int kh  = ks * 16 + ((lane >> 4) << 3);
                uint32_t ad = s2u(&As[p * STG + swA(row, kh)]);
                asm volatile("ldmatrix.sync.aligned.m8n8.x4.shared.b16 {%0,%1,%2,%3}, [%4];"
                    : "=r"(af[i][0]), "=r"(af[i][1]), "=r"(af[i][2]), "=r"(af[i][3])
                    : "r"(ad));
            }
            uint32_t bf[8][2];
            #pragma unroll
            for (int j2 = 0; j2 < 4; j2++) {
                int row = wn + j2 * 16 + (lane & 7) + (((lane >> 4) & 1) << 3);
                int kh  = ks * 16 + (((lane >> 3) & 1) << 3);
                uint32_t bd = s2u(&Bs[p * STG + swA(row, kh)]);
                asm volatile("ldmatrix.sync.aligned.m8n8.x4.shared.b16 {%0,%1,%2,%3}, [%4];"
                    : "=r"(bf[j2 * 2][0]), "=r"(bf[j2 * 2][1]),
                      "=r"(bf[j2 * 2 + 1][0]), "=r"(bf[j2 * 2 + 1][1])
                    : "r"(bd));
            }
            #pragma unroll
            for (int i = 0; i < 2; i++)
                #pragma unroll
                for (int j = 0; j < 8; j++)
                    asm volatile(
                        "mma.sync.aligned.m16n8k16.row.col.f32.bf16.bf16.f32 "
                        "{%0,%1,%2,%3}, {%4,%5,%6,%7}, {%8,%9}, {%0,%1,%2,%3};"
                        : "+f"(acc[i][j][0]), "+f"(acc[i][j][1]),
                          "+f"(acc[i][j][2]), "+f"(acc[i][j][3])
                        : "r"(af[i][0]), "r"(af[i][1]), "r"(af[i][2]), "r"(af[i][3]),
                          "r"(bf[j][0]), "r"(bf[j][1]));
        }
        p = (p == 2) ? 0 : p + 1;
        pw = (pw == 2) ? 0 : pw + 1;
    }
    __syncthreads();   // all warps done reading stages before T overwrites them

    // ---- stage fp32 tile (diag zeroed) in SMEM ----
    const int gr = lane >> 2, gc = (lane & 3) << 1;
    #pragma unroll
    for (int i = 0; i < 2; i++) {
        const int rl = wm + i * 16 + gr;
        #pragma unroll
        for (int j = 0; j < 8; j++) {
            const int cl = wn + j * 8 + gc;
            const int gofs = (row0 + rl) - (col0 + cl);
            T[rl * 129 + cl]           = (gofs == 0)  ? 0.f : acc[i][j][0];
            T[rl * 129 + cl + 1]       = (gofs == 1)  ? 0.f : acc[i][j][1];
            T[(rl + 8) * 129 + cl]     = (gofs == -8) ? 0.f : acc[i][j][2];
            T[(rl + 8) * 129 + cl + 1] = (gofs == -7) ? 0.f : acc[i][j][3];
        }
    }
    __syncthreads();

    // ---- row pass: write exp(tile) as e4m3 + row-max atomics ----
    {
        const int rr = tid >> 1, cs = (tid & 1) << 6;
        float mx = -INFINITY;
        uint32_t* dst = (uint32_t*)(g_expb + (size_t)b * NN * NN
                                    + (size_t)(row0 + rr) * NN + col0 + cs);
        #pragma unroll
        for (int c = 0; c < 64; c += 4) {
            float v0 = T[rr * 129 + cs + c + 0];
            float v1 = T[rr * 129 + cs + c + 1];
            float v2 = T[rr * 129 + cs + c + 2];
            float v3 = T[rr * 129 + cs + c + 3];
            mx = fmaxf(mx, fmaxf(fmaxf(v0, v1), fmaxf(v2, v3)));
            dst[c >> 2] = pk4f8(__expf(v0), __expf(v1), __expf(v2), __expf(v3));
        }
        atomicMax(&g_confbits[b * NN + row0 + rr], fenc(mx));
    }

    // ---- col pass (mirror) for off-diagonal tiles ----
    if (!diag) {
        const int cc = tid >> 1, rs = (tid & 1) << 6;
        float mx = -INFINITY;
        uint32_t* dst = (uint32_t*)(g_expb + (size_t)b * NN * NN
                                    + (size_t)(col0 + cc) * NN + row0 + rs);
        #pragma unroll
        for (int r = 0; r < 64; r += 4) {
            float v0 = T[(rs + r + 0) * 129 + cc];
            float v1 = T[(rs + r + 1) * 129 + cc];
            float v2 = T[(rs + r + 2) * 129 + cc];
            float v3 = T[(rs + r + 3) * 129 + cc];
            mx = fmaxf(mx, fmaxf(fmaxf(v0, v1), fmaxf(v2, v3)));
            dst[r >> 2] = pk4f8(__expf(v0), __expf(v1), __expf(v2), __expf(v3));
        }
        atomicMax(&g_confbits[b * NN + col0 + cc], fenc(mx));
    }
}

// ---------------------------------------------------------------------------
// Kernel 3: row sums of e4m3 exp -> rinv; conf from confbits.
// ---------------------------------------------------------------------------
__global__ void rowsum_kernel() {
    const int row = blockIdx.x;
    const uint4* p = (const uint4*)(g_expb + (size_t)row * NN) + threadIdx.x;
    uint4 v = p[0];
    float s = 0.f;
    const uint32_t w4[4] = {v.x, v.y, v.z, v.w};
    #pragma unroll
    for (int h = 0; h < 4; h++) {
        float2 a = up2f8((uint16_t)(w4[h] & 0xFFFF));
        float2 b2 = up2f8((uint16_t)(w4[h] >> 16));
        s += (a.x + a.y) + (b2.x + b2.y);
    }
    __shared__ float sh[4];
    #pragma unroll
    for (int o = 16; o > 0; o >>= 1) s += __shfl_xor_sync(0xffffffffu, s, o);
    const int w = threadIdx.x >> 5, l = threadIdx.x & 31;
    if (l == 0) sh[w] = s;
    __syncthreads();
    if (threadIdx.x == 0) {
        float v2 = sh[0] + sh[1] + sh[2] + sh[3];
        g_conf[row] = fdec(g_confbits[row]);
        g_rinv[row] = 1.0f / v2;
    }
}

// ---------------------------------------------------------------------------
// Kernel 4: refined = (E @ F) * rinv ; out = cw*refined + (1-cw)*final.
// fp8 e4m3 QMMA m16n8k32, k-chunk = 64 bytes, 3-stage pipeline, 1 sync/iter.
// ---------------------------------------------------------------------------
#define KT_OUT (NN / 64)                   // 32 iterations
#define STG8   8192                        // bytes per stage tile (128x64)
#define OUT_SMEM (6 * STG8)                // 49152

__global__ __launch_bounds__(256) void out_mma(const float* __restrict__ fin,
                                               float* __restrict__ out) {
    extern __shared__ char dsm[];
    unsigned char* Es = (unsigned char*)dsm;          // [3][STG8]
    unsigned char* Fs = Es + 3 * STG8;                // [3][STG8]
    const int b = blockIdx.z;
    const int row0 = blockIdx.y << 7;   // n rows
    const int col0 = blockIdx.x << 7;   // d cols
    const unsigned char* Eb = g_expb + (size_t)b * NN * NN;
    const unsigned char* Tb = g_ftp8 + (size_t)b * DD * NN;

    const int tid = threadIdx.x, lane = tid & 31, wid = tid >> 5;
    const int wm = (wid >> 1) << 5;
    const int wn = (wid & 1) << 6;

    float acc[2][8][4];
    #pragma unroll
    for (int i = 0; i < 2; i++)
        #pragma unroll
        for (int j = 0; j < 8; j++)
            #pragma unroll
            for (int k = 0; k < 4; k++) acc[i][j][k] = 0.f;

    // 512 16B chunks per tile; 2 per thread
    const int r0c = tid >> 2,          c0c = tid & 3;
    const int r1c = (tid + 256) >> 2,  c1c = (tid + 256) & 3;

    #define OUT_LOAD(kt, p)                                                           \
        do {                                                                          \
            cpa16(&Es[(p) * STG8 + off8(r0c, c0c)], Eb + (size_t)(row0 + r0c) * NN + (kt) + c0c * 16); \
            cpa16(&Es[(p) * STG8 + off8(r1c, c1c)], Eb + (size_t)(row0 + r1c) * NN + (kt) + c1c * 16); \
            cpa16(&Fs[(p) * STG8 + off8(r0c, c0c)], Tb + (size_t)(col0 + r0c) * NN + (kt) + c0c * 16); \
            cpa16(&Fs[(p) * STG8 + off8(r1c, c1c)], Tb + (size_t)(col0 + r1c) * NN + (kt) + c1c * 16); \
        } while (0)

    OUT_LOAD(0, 0);
    CP_COMMIT();
    OUT_LOAD(64, 1);
    CP_COMMIT();

    int p = 0, pw = 2;
    for (int kti = 0; kti < KT_OUT; kti++) {
        CP_WAIT(1);
        __syncthreads();
        if (kti + 2 < KT_OUT) OUT_LOAD((kti + 2) * 64, pw);
        CP_COMMIT();

        #pragma unroll
        for (int ks = 0; ks < 2; ks++) {
            uint32_t af[2][4];
            #pragma unroll
            for (int i = 0; i < 2; i++) {
                int row = wm + i * 16 + (lane & 15);
                int c16 = ks * 2 + (lane >> 4);
                uint32_t ad = s2u(&Es[p * STG8 + off8(row, c16)]);
                asm volatile("ldmatrix.sync.aligned.m8n8.x4.shared.b16 {%0,%1,%2,%3}, [%4];"
                    : "=r"(af[i][0]), "=r"(af[i][1]), "=r"(af[i][2]), "=r"(af[i][3])
                    : "r"(ad));
            }
            uint32_t bf[8][2];
            #pragma unroll
            for (int j2 = 0; j2 < 4; j2++) {
                int row = wn + j2 * 16 + (lane & 7) + (((lane >> 4) & 1) << 3);
                int c16 = ks * 2 + ((lane >> 3) & 1);
                uint32_t bd = s2u(&Fs[p * STG8 + off8(row, c16)]);
                asm volatile("ldmatrix.sync.aligned.m8n8.x4.shared.b16 {%0,%1,%2,%3}, [%4];"
                    : "=r"(bf[j2 * 2][0]), "=r"(bf[j2 * 2][1]),
                      "=r"(bf[j2 * 2 + 1][0]), "=r"(bf[j2 * 2 + 1][1])
                    : "r"(bd));
            }
            #pragma unroll
            for (int i = 0; i < 2; i++)
                #pragma unroll
                for (int j = 0; j < 8; j++)
                    asm volatile(
                        "mma.sync.aligned.m16n8k32.row.col.f32.e4m3.e4m3.f32 "
                        "{%0,%1,%2,%3}, {%4,%5,%6,%7}, {%8,%9}, {%0,%1,%2,%3};"
                        : "+f"(acc[i][j][0]), "+f"(acc[i][j][1]),
                          "+f"(acc[i][j][2]), "+f"(acc[i][j][3])
                        : "r"(af[i][0]), "r"(af[i][1]), "r"(af[i][2]), "r"(af[i][3]),
                          "r"(bf[j][0]), "r"(bf[j][1]));
        }
        p = (p == 2) ? 0 : p + 1;
        pw = (pw == 2) ? 0 : pw + 1;
    }

    const float* F32 = fin + (size_t)b * NN * DD;
    float* O = out + (size_t)b * NN * DD;
    const int gr = lane >> 2, gc = (lane & 3) << 1;
    #pragma unroll
    for (int i = 0; i < 2; i++) {
        #pragma unroll
        for (int half = 0; half < 2; half++) {
            int r = row0 + wm + i * 16 + gr + half * 8;
            const float cw  = g_conf[b * NN + r];
            const float inv = g_rinv[b * NN + r];
            #pragma unroll
            for (int j = 0; j < 8; j++) {
                int c = col0 + wn + j * 8 + gc;
                float2 f = *(const float2*)(F32 + (size_t)r * DD + c);
                float2 o;
                o.x = cw * (acc[i][j][half * 2 + 0] * inv) + (1.0f - cw) * f.x;
                o.y = cw * (acc[i][j][half * 2 + 1] * inv) + (1.0f - cw) * f.y;
                *(float2*)(O + (size_t)r * DD + c) = o;
            }
        }
    }
}

// ---------------------------------------------------------------------------
extern "C" void kernel_launch(void* const* d_in, const int* in_sizes, int n_in,
                              void* d_out, int out_size) {
    const float* final_f = (const float*)d_in[0];
    const float* mid_f   = (const float*)d_in[1];
    float* out = (float*)d_out;

    static int configured = 0;
    if (!configured) {
        cudaFuncSetAttribute(sim_mma, cudaFuncAttributeMaxDynamicSharedMemorySize,
                             SIM_SMEM);
        cudaFuncSetAttribute(out_mma, cudaFuncAttributeMaxDynamicSharedMemorySize,
                             OUT_SMEM);
        configured = 1;
    }

    norm_kernel<<<BATCH * NN, 256>>>(mid_f);
    transpose_fp8<<<dim3(DD / 32, NN / 32, BATCH), dim3(32, 8)>>>(final_f);

    sim_mma<<<dim3(NPAIRS, 1, BATCH), 256, SIM_SMEM>>>();

    rowsum_kernel<<<BATCH * NN, 128>>>();

    out_mma<<<dim3(DD / 128, NN / 128, BATCH), 256, OUT_SMEM>>>(final_f, out);
}

// round 11
// speedup vs baseline: 1.3752x; 1.1933x over previous
#include <cuda_runtime.h>
#include <cuda_bf16.h>
#include <cuda_fp8.h>
#include <stdint.h>
#include <stddef.h>
#include <math.h>

#define BATCH 8
#define NN 2048
#define DD 768
#define NTILE 16
#define NPAIRS (NTILE * (NTILE + 1) / 2)   // 136 upper-triangle tiles

// ---------------- device scratch (allocation-free rule) ----------------
__device__ __nv_bfloat16 g_midn[(size_t)BATCH * NN * DD];   // normalized mid (bf16)
__device__ unsigned char g_ftp8[(size_t)BATCH * DD * NN];   // final^T (e4m3), [d][n]
__device__ unsigned char g_expb[(size_t)BATCH * NN * NN];   // e4m3 exp(sim)
__device__ unsigned      g_confbits[BATCH * NN];            // ordered-uint row max
__device__ float         g_conf[BATCH * NN];                // row max (confidence)
__device__ float         g_rinv[BATCH * NN];                // 1 / row sum of exp

__device__ __forceinline__ uint32_t s2u(const void* p) {
    return (uint32_t)__cvta_generic_to_shared(p);
}
__device__ __forceinline__ void cpa16(void* dst, const void* src) {
    asm volatile("cp.async.cg.shared.global [%0], [%1], 16;"
                 :: "r"(s2u(dst)), "l"(src));
}
#define CP_COMMIT() asm volatile("cp.async.commit_group;")
#define CP_WAIT(n)  asm volatile("cp.async.wait_group %0;" :: "n"(n))

// monotonic float<->uint for atomicMax
__device__ __forceinline__ unsigned fenc(float x) {
    unsigned b = __float_as_uint(x);
    return (b & 0x80000000u) ? ~b : (b | 0x80000000u);
}
__device__ __forceinline__ float fdec(unsigned e) {
    unsigned b = (e & 0x80000000u) ? (e ^ 0x80000000u) : ~e;
    return __uint_as_float(b);
}
__device__ __forceinline__ uint32_t pk2f8(float a, float b2) {
    return (uint32_t)__nv_cvt_float2_to_fp8x2(make_float2(a, b2),
                                              __NV_SATFINITE, __NV_E4M3);
}
__device__ __forceinline__ uint32_t pk4f8(float a, float b2, float c, float d) {
    return pk2f8(a, b2) | (pk2f8(c, d) << 16);
}
__device__ __forceinline__ float2 up2f8(uint16_t x) {
    __half2_raw hr = __nv_cvt_fp8x2_to_halfraw2((__nv_fp8x2_storage_t)x, __NV_E4M3);
    return __half22float2(*(__half2*)&hr);
}

// swizzled index (halves) for bf16 tiles: 128 rows x 32 halves (64B rows)
__device__ __forceinline__ int swA(int row, int kh) {
    return (row << 5) | ((((kh >> 3) ^ ((row >> 1) & 3)) << 3));
}
// swizzled byte offset for fp8 tiles: 128 rows x 64 bytes, 16B chunks
__device__ __forceinline__ int off8(int r, int c16) {
    return (r << 6) | ((((c16) ^ ((r >> 1) & 3)) & 3) << 4);
}

// ---------------------------------------------------------------------------
// Kernel 1: L2-normalize mid along D -> bf16; reset g_confbits.
// ---------------------------------------------------------------------------
__global__ void norm_kernel(const float* __restrict__ mid) {
    const int row = blockIdx.x;
    if (threadIdx.x == 0) g_confbits[row] = fenc(-INFINITY);
    const float* x = mid + (size_t)row * DD;
    __nv_bfloat16* y = g_midn + (size_t)row * DD;

    float s = 0.f;
    for (int i = threadIdx.x; i < DD; i += blockDim.x) {
        float v = x[i];
        s += v * v;
    }
    __shared__ float sh[32];
    #pragma unroll
    for (int o = 16; o > 0; o >>= 1) s += __shfl_xor_sync(0xffffffffu, s, o);
    const int w = threadIdx.x >> 5, l = threadIdx.x & 31;
    if (l == 0) sh[w] = s;
    __syncthreads();
    if (w == 0) {
        float v = (threadIdx.x < (blockDim.x >> 5)) ? sh[threadIdx.x] : 0.f;
        #pragma unroll
        for (int o = 16; o > 0; o >>= 1) v += __shfl_xor_sync(0xffffffffu, v, o);
        if (threadIdx.x == 0) sh[0] = v;
    }
    __syncthreads();
    const float inv = 1.0f / fmaxf(sqrtf(sh[0]), 1e-12f);
    for (int i = threadIdx.x; i < DD; i += blockDim.x)
        y[i] = __float2bfloat16(x[i] * inv);
}

// ---------------------------------------------------------------------------
// Kernel 1b: transpose final fp32 [n][d] -> e4m3 [d][n].
// ---------------------------------------------------------------------------
__global__ void transpose_fp8(const float* __restrict__ fin) {
    __shared__ float t[32][33];
    const int b = blockIdx.z;
    const int d0 = blockIdx.x * 32, n0 = blockIdx.y * 32;
    const float* F = fin + (size_t)b * NN * DD;
    unsigned char* T = g_ftp8 + (size_t)b * DD * NN;
    const int x = threadIdx.x, y = threadIdx.y;
    #pragma unroll
    for (int i = 0; i < 4; i++)
        t[y + 8 * i][x] = F[(size_t)(n0 + y + 8 * i) * DD + d0 + x];
    __syncthreads();
    uint32_t word = pk4f8(t[y * 4 + 0][x], t[y * 4 + 1][x],
                          t[y * 4 + 2][x], t[y * 4 + 3][x]);
    *(uint32_t*)(T + (size_t)(d0 + x) * NN + n0 + y * 4) = word;
}

// ---------------------------------------------------------------------------
// Kernel 2: sim GEMM (upper-triangle tiles, bf16 HMMA). 128x128 CTA tile,
// 4 warps (64x64 warp tile), k-chunk 32 halves, 3-stage pipeline.
// Epilogue: exp(sim) e4m3 + row-max atomics, symmetric mirror.
// ---------------------------------------------------------------------------
#define KT_SIM (DD / 32)                   // 24 iterations
#define STG    4096                        // halves per stage tile (128x32)
#define SIM_SMEM (128 * 129 * 4)           // 66048 B (>= 3 stages * 16KB = 49152)

__global__ __launch_bounds__(128) void sim_mma() {
    extern __shared__ char dsm[];
    __nv_bfloat16* As = (__nv_bfloat16*)dsm;          // [3][STG]
    __nv_bfloat16* Bs = As + 3 * STG;                 // [3][STG]
    float* T = (float*)dsm;                           // [128][129], reused

    int t = blockIdx.x, bi = 0, rem = NTILE;
    while (t >= rem) { t -= rem; rem--; bi++; }
    const int bj = bi + t;
    const int b = blockIdx.z;
    const int row0 = bi << 7, col0 = bj << 7;
    const bool diag = (bi == bj);
    const __nv_bfloat16* Ab = g_midn + (size_t)b * NN * DD;

    const int tid = threadIdx.x, lane = tid & 31, wid = tid >> 5;
    const int wm = (wid >> 1) << 6;    // 0, 64
    const int wn = (wid & 1) << 6;     // 0, 64

    float acc[4][8][4];
    #pragma unroll
    for (int i = 0; i < 4; i++)
        #pragma unroll
        for (int j = 0; j < 8; j++)
            #pragma unroll
            for (int k = 0; k < 4; k++) acc[i][j][k] = 0.f;

    // loader: 512 16B-chunks per tile, 4 per thread per operand
    // chunk = tid + 128*q: r = chunk>>2 (row), c = chunk&3 (16B col)
    #define SIM_LOAD(kt, p)                                                     \
        do {                                                                    \
            _Pragma("unroll")                                                   \
            for (int q = 0; q < 4; q++) {                                       \
                int ch = tid + 128 * q;                                         \
                int r = ch >> 2, c = ch & 3;                                    \
                int so = (r << 5) | (((c ^ ((r >> 1) & 3))) << 3);              \
                cpa16(&As[(p) * STG + so],                                      \
                      Ab + (size_t)(row0 + r) * DD + (kt) + c * 8);             \
                cpa16(&Bs[(p) * STG + so],                                      \
                      Ab + (size_t)(col0 + r) * DD + (kt) + c * 8);             \
            }                                                                   \
        } while (0)

    SIM_LOAD(0, 0);
    CP_COMMIT();
    SIM_LOAD(32, 1);
    CP_COMMIT();

    int p = 0, pw = 2;
    for (int kti = 0; kti < KT_SIM; kti++) {
        CP_WAIT(1);
        __syncthreads();
        if (kti + 2 < KT_SIM) SIM_LOAD((kti + 2) * 32, pw);
        CP_COMMIT();

        #pragma unroll
        for (int ks = 0; ks < 2; ks++) {
            uint32_t af[4][4];
            #pragma unroll
            for (int i = 0; i < 4; i++) {
                int row = wm + i * 16 + (lane & 15);
                int kh  = ks * 16 + ((lane >> 4) << 3);
                uint32_t ad = s2u(&As[p * STG + swA(row, kh)]);
                asm volatile("ldmatrix.sync.aligned.m8n8.x4.shared.b16 {%0,%1,%2,%3}, [%4];"
                    : "=r"(af[i][0]), "=r"(af[i][1]), "=r"(af[i][2]), "=r"(af[i][3])
                    : "r"(ad));
            }
            uint32_t bf[8][2];
            #pragma unroll
            for (int j2 = 0; j2 < 4; j2++) {
                int row = wn + j2 * 16 + (lane & 7) + (((lane >> 4) & 1) << 3);
                int kh  = ks * 16 + (((lane >> 3) & 1) << 3);
                uint32_t bd = s2u(&Bs[p * STG + swA(row, kh)]);
                asm volatile("ldmatrix.sync.aligned.m8n8.x4.shared.b16 {%0,%1,%2,%3}, [%4];"
                    : "=r"(bf[j2 * 2][0]), "=r"(bf[j2 * 2][1]),
                      "=r"(bf[j2 * 2 + 1][0]), "=r"(bf[j2 * 2 + 1][1])
                    : "r"(bd));
            }
            #pragma unroll
            for (int i = 0; i < 4; i++)
                #pragma unroll
                for (int j = 0; j < 8; j++)
                    asm volatile(
                        "mma.sync.aligned.m16n8k16.row.col.f32.bf16.bf16.f32 "
                        "{%0,%1,%2,%3}, {%4,%5,%6,%7}, {%8,%9}, {%0,%1,%2,%3};"
                        : "+f"(acc[i][j][0]), "+f"(acc[i][j][1]),
                          "+f"(acc[i][j][2]), "+f"(acc[i][j][3])
                        : "r"(af[i][0]), "r"(af[i][1]), "r"(af[i][2]), "r"(af[i][3]),
                          "r"(bf[j][0]), "r"(bf[j][1]));
        }
        p = (p == 2) ? 0 : p + 1;
        pw = (pw == 2) ? 0 : pw + 1;
    }
    __syncthreads();   // all warps done reading stages before T overwrites them

    // ---- stage fp32 tile (diag zeroed) in SMEM ----
    const int gr = lane >> 2, gc = (lane & 3) << 1;
    #pragma unroll
    for (int i = 0; i < 4; i++) {
        const int rl = wm + i * 16 + gr;
        #pragma unroll
        for (int j = 0; j < 8; j++) {
            const int cl = wn + j * 8 + gc;
            const int gofs = (row0 + rl) - (col0 + cl);
            T[rl * 129 + cl]           = (gofs == 0)  ? 0.f : acc[i][j][0];
            T[rl * 129 + cl + 1]       = (gofs == 1)  ? 0.f : acc[i][j][1];
            T[(rl + 8) * 129 + cl]     = (gofs == -8) ? 0.f : acc[i][j][2];
            T[(rl + 8) * 129 + cl + 1] = (gofs == -7) ? 0.f : acc[i][j][3];
        }
    }
    __syncthreads();

    // ---- row pass: write exp(tile) as e4m3 + row-max atomics ----
    {
        const int rr = tid;                 // one row per thread
        float mx = -INFINITY;
        uint32_t* dst = (uint32_t*)(g_expb + (size_t)b * NN * NN
                                    + (size_t)(row0 + rr) * NN + col0);
        #pragma unroll
        for (int c = 0; c < 128; c += 4) {
            float v0 = T[rr * 129 + c + 0];
            float v1 = T[rr * 129 + c + 1];
            float v2 = T[rr * 129 + c + 2];
            float v3 = T[rr * 129 + c + 3];
            mx = fmaxf(mx, fmaxf(fmaxf(v0, v1), fmaxf(v2, v3)));
            dst[c >> 2] = pk4f8(__expf(v0), __expf(v1), __expf(v2), __expf(v3));
        }
        atomicMax(&g_confbits[b * NN + row0 + rr], fenc(mx));
    }

    // ---- col pass (mirror) for off-diagonal tiles ----
    if (!diag) {
        const int cc = tid;                 // one column per thread
        float mx = -INFINITY;
        uint32_t* dst = (uint32_t*)(g_expb + (size_t)b * NN * NN
                                    + (size_t)(col0 + cc) * NN + row0);
        #pragma unroll
        for (int r = 0; r < 128; r += 4) {
            float v0 = T[(r + 0) * 129 + cc];
            float v1 = T[(r + 1) * 129 + cc];
            float v2 = T[(r + 2) * 129 + cc];
            float v3 = T[(r + 3) * 129 + cc];
            mx = fmaxf(mx, fmaxf(fmaxf(v0, v1), fmaxf(v2, v3)));
            dst[r >> 2] = pk4f8(__expf(v0), __expf(v1), __expf(v2), __expf(v3));
        }
        atomicMax(&g_confbits[b * NN + col0 + cc], fenc(mx));
    }
}

// ---------------------------------------------------------------------------
// Kernel 3: row sums of e4m3 exp -> rinv; conf from confbits.
// ---------------------------------------------------------------------------
__global__ void rowsum_kernel() {
    const int row = blockIdx.x;
    const uint4* p = (const uint4*)(g_expb + (size_t)row * NN) + threadIdx.x;
    uint4 v = p[0];
    float s = 0.f;
    const uint32_t w4[4] = {v.x, v.y, v.z, v.w};
    #pragma unroll
    for (int h = 0; h < 4; h++) {
        float2 a = up2f8((uint16_t)(w4[h] & 0xFFFF));
        float2 b2 = up2f8((uint16_t)(w4[h] >> 16));
        s += (a.x + a.y) + (b2.x + b2.y);
    }
    __shared__ float sh[4];
    #pragma unroll
    for (int o = 16; o > 0; o >>= 1) s += __shfl_xor_sync(0xffffffffu, s, o);
    const int w = threadIdx.x >> 5, l = threadIdx.x & 31;
    if (l == 0) sh[w] = s;
    __syncthreads();
    if (threadIdx.x == 0) {
        float v2 = sh[0] + sh[1] + sh[2] + sh[3];
        g_conf[row] = fdec(g_confbits[row]);
        g_rinv[row] = 1.0f / v2;
    }
}

// ---------------------------------------------------------------------------
// Kernel 4: refined = (E @ F) * rinv ; out = cw*refined + (1-cw)*final.
// fp8 e4m3 QMMA m16n8k32. 128x128 CTA tile, 4 warps (64x64 warp tile),
// k-chunk 64 bytes, 3-stage pipeline.
// ---------------------------------------------------------------------------
#define KT_OUT (NN / 64)                   // 32 iterations
#define STG8   8192                        // bytes per stage tile (128x64)
#define OUT_SMEM (6 * STG8)                // 49152

__global__ __launch_bounds__(128) void out_mma(const float* __restrict__ fin,
                                               float* __restrict__ out) {
    extern __shared__ char dsm[];
    unsigned char* Es = (unsigned char*)dsm;          // [3][STG8]
    unsigned char* Fs = Es + 3 * STG8;                // [3][STG8]
    const int b = blockIdx.z;
    const int row0 = blockIdx.y << 7;   // n rows
    const int col0 = blockIdx.x << 7;   // d cols
    const unsigned char* Eb = g_expb + (size_t)b * NN * NN;
    const unsigned char* Tb = g_ftp8 + (size_t)b * DD * NN;

    const int tid = threadIdx.x, lane = tid & 31, wid = tid >> 5;
    const int wm = (wid >> 1) << 6;
    const int wn = (wid & 1) << 6;

    float acc[4][8][4];
    #pragma unroll
    for (int i = 0; i < 4; i++)
        #pragma unroll
        for (int j = 0; j < 8; j++)
            #pragma unroll
            for (int k = 0; k < 4; k++) acc[i][j][k] = 0.f;

    // loader: 512 16B-chunks per tile, 4 per thread per operand
    #define OUT_LOAD(kt, p)                                                     \
        do {                                                                    \
            _Pragma("unroll")                                                   \
            for (int q = 0; q < 4; q++) {                                       \
                int ch = tid + 128 * q;                                         \
                int r = ch >> 2, c = ch & 3;                                    \
                int so = off8(r, c);                                            \
                cpa16(&Es[(p) * STG8 + so],                                     \
                      Eb + (size_t)(row0 + r) * NN + (kt) + c * 16);            \
                cpa16(&Fs[(p) * STG8 + so],                                     \
                      Tb + (size_t)(col0 + r) * NN + (kt) + c * 16);            \
            }                                                                   \
        } while (0)

    OUT_LOAD(0, 0);
    CP_COMMIT();
    OUT_LOAD(64, 1);
    CP_COMMIT();

    int p = 0, pw = 2;
    for (int kti = 0; kti < KT_OUT; kti++) {
        CP_WAIT(1);
        __syncthreads();
        if (kti + 2 < KT_OUT) OUT_LOAD((kti + 2) * 64, pw);
        CP_COMMIT();

        #pragma unroll
        for (int ks = 0; ks < 2; ks++) {
            uint32_t af[4][4];
            #pragma unroll
            for (int i = 0; i < 4; i++) {
                int row = wm + i * 16 + (lane & 15);
                int c16 = ks * 2 + (lane >> 4);
                uint32_t ad = s2u(&Es[p * STG8 + off8(row, c16)]);
                asm volatile("ldmatrix.sync.aligned.m8n8.x4.shared.b16 {%0,%1,%2,%3}, [%4];"
                    : "=r"(af[i][0]), "=r"(af[i][1]), "=r"(af[i][2]), "=r"(af[i][3])
                    : "r"(ad));
            }
            uint32_t bf[8][2];
            #pragma unroll
            for (int j2 = 0; j2 < 4; j2++) {
                int row = wn + j2 * 16 + (lane & 7) + (((lane >> 4) & 1) << 3);
                int c16 = ks * 2 + ((lane >> 3) & 1);
                uint32_t bd = s2u(&Fs[p * STG8 + off8(row, c16)]);
                asm volatile("ldmatrix.sync.aligned.m8n8.x4.shared.b16 {%0,%1,%2,%3}, [%4];"
                    : "=r"(bf[j2 * 2][0]), "=r"(bf[j2 * 2][1]),
                      "=r"(bf[j2 * 2 + 1][0]), "=r"(bf[j2 * 2 + 1][1])
                    : "r"(bd));
            }
            #pragma unroll
            for (int i = 0; i < 4; i++)
                #pragma unroll
                for (int j = 0; j < 8; j++)
                    asm volatile(
                        "mma.sync.aligned.m16n8k32.row.col.f32.e4m3.e4m3.f32 "
                        "{%0,%1,%2,%3}, {%4,%5,%6,%7}, {%8,%9}, {%0,%1,%2,%3};"
                        : "+f"(acc[i][j][0]), "+f"(acc[i][j][1]),
                          "+f"(acc[i][j][2]), "+f"(acc[i][j][3])
                        : "r"(af[i][0]), "r"(af[i][1]), "r"(af[i][2]), "r"(af[i][3]),
                          "r"(bf[j][0]), "r"(bf[j][1]));
        }
        p = (p == 2) ? 0 : p + 1;
        pw = (pw == 2) ? 0 : pw + 1;
    }

    const float* F32 = fin + (size_t)b * NN * DD;
    float* O = out + (size_t)b * NN * DD;
    const int gr = lane >> 2, gc = (lane & 3) << 1;
    #pragma unroll
    for (int i = 0; i < 4; i++) {
        #pragma unroll
        for (int half = 0; half < 2; half++) {
            int r = row0 + wm + i * 16 + gr + half * 8;
            const float cw  = g_conf[b * NN + r];
            const float inv = g_rinv[b * NN + r];
            #pragma unroll
            for (int j = 0; j < 8; j++) {
                int c = col0 + wn + j * 8 + gc;
                float2 f = *(const float2*)(F32 + (size_t)r * DD + c);
                float2 o;
                o.x = cw * (acc[i][j][half * 2 + 0] * inv) + (1.0f - cw) * f.x;
                o.y = cw * (acc[i][j][half * 2 + 1] * inv) + (1.0f - cw) * f.y;
                *(float2*)(O + (size_t)r * DD + c) = o;
            }
        }
    }
}

// ---------------------------------------------------------------------------
extern "C" void kernel_launch(void* const* d_in, const int* in_sizes, int n_in,
                              void* d_out, int out_size) {
    const float* final_f = (const float*)d_in[0];
    const float* mid_f   = (const float*)d_in[1];
    float* out = (float*)d_out;

    static int configured = 0;
    if (!configured) {
        cudaFuncSetAttribute(sim_mma, cudaFuncAttributeMaxDynamicSharedMemorySize,
                             SIM_SMEM);
        cudaFuncSetAttribute(out_mma, cudaFuncAttributeMaxDynamicSharedMemorySize,
                             OUT_SMEM);
        configured = 1;
    }

    norm_kernel<<<BATCH * NN, 256>>>(mid_f);
    transpose_fp8<<<dim3(DD / 32, NN / 32, BATCH), dim3(32, 8)>>>(final_f);

    sim_mma<<<dim3(NPAIRS, 1, BATCH), 128, SIM_SMEM>>>();

    rowsum_kernel<<<BATCH * NN, 128>>>();

    out_mma<<<dim3(DD / 128, NN / 128, BATCH), 128, OUT_SMEM>>>(final_f, out);
}